// round 4
// baseline (speedup 1.0000x reference)
#include <cuda_runtime.h>

// Output = 1.0f everywhere (analytic reduction: the circuit is diagonal RZ
// phases + CNOT basis permutations acting on |0...0>; every CNOT fixes basis
// index 0, so the state remains |0...0> up to a global phase and <Z_i> = +1
// for all wires, independent of inputs and weights).
//
// Launch-overhead-bound fill. Single wave: 128 CTAs (< 148 SMs), 512 threads,
// 2 independent STG.128 per thread, branch-free.

__global__ __launch_bounds__(512) void fill_ones_w512(float4* __restrict__ out) {
    const float4 ones = make_float4(1.0f, 1.0f, 1.0f, 1.0f);
    unsigned base = blockIdx.x * 1024u + threadIdx.x;
    out[base]        = ones;
    out[base + 512]  = ones;
}

// Generic fallback for sizes not divisible by 4096 floats.
__global__ __launch_bounds__(256) void fill_ones_generic(float* __restrict__ out, int n) {
    int i = blockIdx.x * 256 + threadIdx.x;
    for (; i < n; i += gridDim.x * 256) out[i] = 1.0f;
}

extern "C" void kernel_launch(void* const* d_in, const int* in_sizes, int n_in,
                              void* d_out, int out_size) {
    (void)d_in; (void)in_sizes; (void)n_in;
    float* out = (float*)d_out;

    // Fast path: out_size divisible by 512 threads * 2 float4 * 4 floats = 4096.
    if ((out_size & 4095) == 0 && out_size > 0) {
        int blocks = out_size >> 12;                 // 524288 -> 128 blocks
        fill_ones_w512<<<blocks, 512>>>((float4*)out);
    } else {
        int blocks = (out_size + 255) / 256;
        if (blocks > 1184) blocks = 1184;
        fill_ones_generic<<<blocks, 256>>>(out, out_size);
    }
}

// round 5
// speedup vs baseline: 1.0337x; 1.0337x over previous
#include <cuda_runtime.h>

// Output = 1.0f everywhere (analytic reduction: the circuit is diagonal RZ
// phases + CNOT basis permutations acting on |0...0>; every CNOT fixes basis
// index 0, so the state remains |0...0> up to a global phase and <Z_i> = +1
// for all wires, independent of inputs and weights).
//
// Best-measured shape across 4 profiled variants: single wave of 128 CTAs
// (< 148 SMs), 256 threads, 4 independent STG.128 per thread (MLP=4),
// branch-free. Kernel duration is launch/ramp-overhead bound (~3.6us); the
// 2 MiB of stores is ~0.2us of L2 traffic underneath it.

__global__ __launch_bounds__(256) void fill_ones_x4(float4* __restrict__ out) {
    const float4 ones = make_float4(1.0f, 1.0f, 1.0f, 1.0f);
    unsigned base = blockIdx.x * 1024u + threadIdx.x;
    out[base]        = ones;
    out[base + 256]  = ones;
    out[base + 512]  = ones;
    out[base + 768]  = ones;
}

// Generic fallback for sizes not divisible by 4096 floats.
__global__ __launch_bounds__(256) void fill_ones_generic(float* __restrict__ out, int n) {
    int i = blockIdx.x * 256 + threadIdx.x;
    for (; i < n; i += gridDim.x * 256) out[i] = 1.0f;
}

extern "C" void kernel_launch(void* const* d_in, const int* in_sizes, int n_in,
                              void* d_out, int out_size) {
    (void)d_in; (void)in_sizes; (void)n_in;
    float* out = (float*)d_out;

    // Fast path: out_size divisible by 256 threads * 4 float4 * 4 floats = 4096.
    if ((out_size & 4095) == 0 && out_size > 0) {
        int blocks = out_size >> 12;                 // 524288 -> 128 blocks
        fill_ones_x4<<<blocks, 256>>>((float4*)out);
    } else {
        int blocks = (out_size + 255) / 256;
        if (blocks > 1184) blocks = 1184;
        fill_ones_generic<<<blocks, 256>>>(out, out_size);
    }
}